// round 4
// baseline (speedup 1.0000x reference)
#include <cuda_runtime.h>
#include <math.h>

// ---------------------------------------------------------------------------
// SpSpMM: C = A @ B, A,B sparse COO (N=4096, NNZ=131072 each), C dense fp32.
//
// R4: single persistent fused kernel (zero -> build -> spmm) with a software
// grid barrier. Co-residency guaranteed by __launch_bounds__(256,4) and
// grid = 4 * num_SMs. Vectorized COO loads; MLP=2 inner loop (fixed: no
// sentinel overflow — single loop counter with per-entry guards).
// ---------------------------------------------------------------------------

#define NMAX 4096
#define CAP  256           // max nnz per row; Poisson(32) tail => never hit

__device__ int  g_cntA[NMAX];
__device__ int  g_cntB[NMAX];
__device__ int2 g_Abkt[NMAX * CAP];   // .x = col, .y = bits(val)
__device__ int2 g_Bbkt[NMAX * CAP];
__device__ int  g_bar_cnt;            // barrier arrivals (resets each barrier)
__device__ int  g_bar_epoch;          // monotone across graph replays

// Software grid barrier: all blocks co-resident by launch construction.
__device__ __forceinline__ void grid_barrier(int nblocks, int target) {
    __syncthreads();
    if (threadIdx.x == 0) {
        __threadfence();
        int v = atomicAdd(&g_bar_cnt, 1);
        if (v == nblocks - 1) {
            atomicExch(&g_bar_cnt, 0);
            __threadfence();
            atomicAdd(&g_bar_epoch, 1);
        } else {
            while (atomicAdd(&g_bar_epoch, 0) < target) {
#if __CUDA_ARCH__ >= 700
                __nanosleep(64);
#endif
            }
        }
        __threadfence();
    }
    __syncthreads();
}

__global__ void __launch_bounds__(256, 4)
fused_spspmm_kernel(const int* __restrict__ a_idx,
                    const float* __restrict__ a_val, int nnzA,
                    const int* __restrict__ b_idx,
                    const float* __restrict__ b_val, int nnzB,
                    float* __restrict__ C, int n, int nblocks) {
    __shared__ float crow[NMAX];     // dense row accumulator (16 KB)
    __shared__ int   sk[CAP];        // A-entry cols (k)
    __shared__ float sv[CAP];        // A-entry vals
    __shared__ int   sc[CAP];        // cntB[k] prefetched
    __shared__ int   s_epoch0;

    const int tid      = threadIdx.x;
    const int gt       = blockIdx.x * 256 + tid;
    const int nthreads = nblocks * 256;
    const int warp     = tid >> 5;
    const int lane     = tid & 31;

    if (tid == 0) s_epoch0 = atomicAdd(&g_bar_epoch, 0);  // stable at entry

    // ---- phase 0: zero counters -----------------------------------------
    for (int t = gt; t < n; t += nthreads) { g_cntA[t] = 0; g_cntB[t] = 0; }
    grid_barrier(nblocks, s_epoch0 + 1);

    // ---- phase 1: build buckets (vectorized int4 COO loads) --------------
    {
        const int quadsA = nnzA >> 2;
        const int quadsB = nnzB >> 2;
        const int tailA  = nnzA & 3;
        const int tailB  = nnzB & 3;
        const int total  = quadsA + quadsB + tailA + tailB;
        for (int t = gt; t < total; t += nthreads) {
            if (t < quadsA) {
                int4   r = ((const int4*)a_idx)[t];
                int4   c = ((const int4*)a_idx)[quadsA + t];   // a_idx + nnzA
                float4 v = ((const float4*)a_val)[t];
                int rr[4] = {r.x, r.y, r.z, r.w};
                int cc[4] = {c.x, c.y, c.z, c.w};
                float vv[4] = {v.x, v.y, v.z, v.w};
                #pragma unroll
                for (int j = 0; j < 4; j++) {
                    int s = atomicAdd(&g_cntA[rr[j]], 1);
                    if (s < CAP)
                        g_Abkt[rr[j] * CAP + s] =
                            make_int2(cc[j], __float_as_int(vv[j]));
                }
            } else if (t < quadsA + quadsB) {
                int u = t - quadsA;
                int4   r = ((const int4*)b_idx)[u];
                int4   c = ((const int4*)b_idx)[quadsB + u];
                float4 v = ((const float4*)b_val)[u];
                int rr[4] = {r.x, r.y, r.z, r.w};
                int cc[4] = {c.x, c.y, c.z, c.w};
                float vv[4] = {v.x, v.y, v.z, v.w};
                #pragma unroll
                for (int j = 0; j < 4; j++) {
                    int s = atomicAdd(&g_cntB[rr[j]], 1);
                    if (s < CAP)
                        g_Bbkt[rr[j] * CAP + s] =
                            make_int2(cc[j], __float_as_int(vv[j]));
                }
            } else if (t < quadsA + quadsB + tailA) {
                int idx = quadsA * 4 + (t - quadsA - quadsB);
                int rr = a_idx[idx], cc = a_idx[nnzA + idx];
                int s = atomicAdd(&g_cntA[rr], 1);
                if (s < CAP)
                    g_Abkt[rr * CAP + s] =
                        make_int2(cc, __float_as_int(a_val[idx]));
            } else {
                int idx = quadsB * 4 + (t - quadsA - quadsB - tailA);
                int rr = b_idx[idx], cc = b_idx[nnzB + idx];
                int s = atomicAdd(&g_cntB[rr], 1);
                if (s < CAP)
                    g_Bbkt[rr * CAP + s] =
                        make_int2(cc, __float_as_int(b_val[idx]));
            }
        }
    }
    grid_barrier(nblocks, s_epoch0 + 2);

    // ---- phase 2: spmm, one row at a time per block ----------------------
    float4* crow4 = reinterpret_cast<float4*>(crow);
    const int nq = n >> 2;

    for (int i = blockIdx.x; i < n; i += nblocks) {
        // zero row accumulator
        for (int j = tid; j < nq; j += 256)
            crow4[j] = make_float4(0.f, 0.f, 0.f, 0.f);

        // stage this row's A bucket + partner counts (one parallel round)
        const int nA = min(g_cntA[i], CAP);
        if (tid < nA) {
            int2 p = g_Abkt[i * CAP + tid];
            sk[tid] = p.x;
            sv[tid] = __int_as_float(p.y);
            sc[tid] = min(g_cntB[p.x], CAP);
        }
        __syncthreads();

        // warp handles A-entries e and e+8 together: both B-bucket loads in
        // flight before the shared atomics (MLP=2).
        for (int e = warp; e < nA; e += 16) {
            const int  e2   = e + 8;
            const bool has2 = (e2 < nA);
            const int   k1 = sk[e];
            const float a1 = sv[e];
            const int   m1 = sc[e];
            const int   k2 = has2 ? sk[e2] : 0;
            const float a2 = has2 ? sv[e2] : 0.f;
            const int   m2 = has2 ? sc[e2] : 0;
            const int   mm = m1 > m2 ? m1 : m2;

            for (int t = lane; t < mm; t += 32) {
                int2 q1, q2;
                const bool l1 = (t < m1);
                const bool l2 = (t < m2);
                if (l1) q1 = g_Bbkt[k1 * CAP + t];
                if (l2) q2 = g_Bbkt[k2 * CAP + t];
                if (l1) atomicAdd(&crow[q1.x], a1 * __int_as_float(q1.y));
                if (l2) atomicAdd(&crow[q2.x], a2 * __int_as_float(q2.y));
            }
        }
        __syncthreads();

        // streaming coalesced row store
        float4* out4 = reinterpret_cast<float4*>(C + (size_t)i * n);
        for (int j = tid; j < nq; j += 256)
            out4[j] = crow4[j];
        __syncthreads();   // crow reused next iteration
    }
}

// ---------------------------------------------------------------------------
extern "C" void kernel_launch(void* const* d_in, const int* in_sizes, int n_in,
                              void* d_out, int out_size) {
    const int*   a_idx = (const int*)  d_in[0];
    const float* a_val = (const float*)d_in[1];
    const int*   b_idx = (const int*)  d_in[2];
    const float* b_val = (const float*)d_in[3];
    float*       C     = (float*)d_out;

    const int nnzA = in_sizes[1];
    const int nnzB = in_sizes[3];
    const int n    = (int)(sqrt((double)out_size) + 0.5);

    int dev = 0, sms = 0;
    cudaGetDevice(&dev);
    cudaDeviceGetAttribute(&sms, cudaDevAttrMultiProcessorCount, dev);
    int nblocks = (sms > 0 ? sms : 1) * 4;   // co-resident by construction

    fused_spspmm_kernel<<<nblocks, 256>>>(a_idx, a_val, nnzA,
                                          b_idx, b_val, nnzB,
                                          C, n, nblocks);
}

// round 5
// speedup vs baseline: 1.2870x; 1.2870x over previous
#include <cuda_runtime.h>
#include <math.h>

// ---------------------------------------------------------------------------
// SpSpMM: C = A @ B, A,B sparse COO (N=4096, NNZ=131072 each), C dense fp32.
//
// R5: split pipeline, each phase tuned:
//   1. cudaMemsetAsync zeroes one contiguous counter block (graph memset node)
//   2. build: int4/float4 vectorized COO loads, ILP=4 bucket scatter
//   3. spmm:  one block per row, 256 thr, full occupancy (8 blk/SM),
//             MLP=2 inner loop, smem atomics, streaming float4 row store
// ---------------------------------------------------------------------------

#define NMAX 4096
#define CAP  256           // max nnz per row; Poisson(32) tail => never hit

__device__ int  g_cnt[2 * NMAX];      // [0,NMAX) = A rows, [NMAX,2N) = B rows
__device__ int2 g_Abkt[NMAX * CAP];   // .x = col, .y = bits(val)
__device__ int2 g_Bbkt[NMAX * CAP];

// ---- 2. build strided buckets (vectorized, 4 entries/thread) ---------------
__global__ void __launch_bounds__(256)
build_kernel(const int* __restrict__ a_idx,
             const float* __restrict__ a_val, int nnzA,
             const int* __restrict__ b_idx,
             const float* __restrict__ b_val, int nnzB) {
    const int quadsA = nnzA >> 2;
    const int quadsB = nnzB >> 2;
    const int tailA  = nnzA & 3;
    const int tailB  = nnzB & 3;
    int t = blockIdx.x * blockDim.x + threadIdx.x;

    if (t < quadsA) {
        int4   r = ((const int4*)a_idx)[t];
        int4   c = ((const int4*)a_idx)[quadsA + t];   // a_idx + nnzA
        float4 v = ((const float4*)a_val)[t];
        int   rr[4] = {r.x, r.y, r.z, r.w};
        int   cc[4] = {c.x, c.y, c.z, c.w};
        float vv[4] = {v.x, v.y, v.z, v.w};
        #pragma unroll
        for (int j = 0; j < 4; j++) {
            int s = atomicAdd(&g_cnt[rr[j]], 1);
            if (s < CAP)
                g_Abkt[rr[j] * CAP + s] = make_int2(cc[j], __float_as_int(vv[j]));
        }
    } else if (t < quadsA + quadsB) {
        int u = t - quadsA;
        int4   r = ((const int4*)b_idx)[u];
        int4   c = ((const int4*)b_idx)[quadsB + u];
        float4 v = ((const float4*)b_val)[u];
        int   rr[4] = {r.x, r.y, r.z, r.w};
        int   cc[4] = {c.x, c.y, c.z, c.w};
        float vv[4] = {v.x, v.y, v.z, v.w};
        #pragma unroll
        for (int j = 0; j < 4; j++) {
            int s = atomicAdd(&g_cnt[NMAX + rr[j]], 1);
            if (s < CAP)
                g_Bbkt[rr[j] * CAP + s] = make_int2(cc[j], __float_as_int(vv[j]));
        }
    } else if (t < quadsA + quadsB + tailA) {
        int idx = quadsA * 4 + (t - quadsA - quadsB);
        int rr = a_idx[idx], cc = a_idx[nnzA + idx];
        int s = atomicAdd(&g_cnt[rr], 1);
        if (s < CAP)
            g_Abkt[rr * CAP + s] = make_int2(cc, __float_as_int(a_val[idx]));
    } else if (t < quadsA + quadsB + tailA + tailB) {
        int idx = quadsB * 4 + (t - quadsA - quadsB - tailA);
        int rr = b_idx[idx], cc = b_idx[nnzB + idx];
        int s = atomicAdd(&g_cnt[NMAX + rr], 1);
        if (s < CAP)
            g_Bbkt[rr * CAP + s] = make_int2(cc, __float_as_int(b_val[idx]));
    }
}

// ---- 3. row-wise SpSpMM: smem accumulator, MLP=2 inner loop ----------------
__global__ void __launch_bounds__(256)
spmm_row_kernel(float* __restrict__ C, int n) {
    extern __shared__ float crow[];      // n floats (16 KB @ n=4096)
    __shared__ int   sk[CAP];            // A-entry cols (k)
    __shared__ float sv[CAP];            // A-entry vals
    __shared__ int   sc[CAP];            // cntB[k] prefetched

    const int i    = blockIdx.x;
    const int tid  = threadIdx.x;
    const int warp = tid >> 5;
    const int lane = tid & 31;
    const int nq   = n >> 2;

    // zero row accumulator (overlaps the staging loads below)
    float4* crow4 = reinterpret_cast<float4*>(crow);
    for (int j = tid; j < nq; j += 256)
        crow4[j] = make_float4(0.f, 0.f, 0.f, 0.f);

    // stage this row's A bucket + partner counts in one parallel round
    const int nA = min(g_cnt[i], CAP);
    if (tid < nA) {
        int2 p = g_Abkt[i * CAP + tid];
        sk[tid] = p.x;
        sv[tid] = __int_as_float(p.y);
        sc[tid] = min(g_cnt[NMAX + p.x], CAP);
    }
    __syncthreads();

    // warp handles A-entries e and e+8 together: both B-bucket loads issued
    // before the shared atomics (MLP=2).
    for (int e = warp; e < nA; e += 16) {
        const int  e2   = e + 8;
        const bool has2 = (e2 < nA);
        const int   k1 = sk[e];
        const float a1 = sv[e];
        const int   m1 = sc[e];
        const int   k2 = has2 ? sk[e2] : 0;
        const float a2 = has2 ? sv[e2] : 0.f;
        const int   m2 = has2 ? sc[e2] : 0;
        const int   mm = m1 > m2 ? m1 : m2;

        for (int t = lane; t < mm; t += 32) {
            int2 q1, q2;
            const bool l1 = (t < m1);
            const bool l2 = (t < m2);
            if (l1) q1 = g_Bbkt[k1 * CAP + t];
            if (l2) q2 = g_Bbkt[k2 * CAP + t];
            if (l1) atomicAdd(&crow[q1.x], a1 * __int_as_float(q1.y));
            if (l2) atomicAdd(&crow[q2.x], a2 * __int_as_float(q2.y));
        }
    }
    __syncthreads();

    // streaming coalesced row store
    float4* out4 = reinterpret_cast<float4*>(C + (size_t)i * n);
    for (int j = tid; j < nq; j += 256)
        out4[j] = crow4[j];
}

// ---------------------------------------------------------------------------
extern "C" void kernel_launch(void* const* d_in, const int* in_sizes, int n_in,
                              void* d_out, int out_size) {
    const int*   a_idx = (const int*)  d_in[0];
    const float* a_val = (const float*)d_in[1];
    const int*   b_idx = (const int*)  d_in[2];
    const float* b_val = (const float*)d_in[3];
    float*       C     = (float*)d_out;

    const int nnzA = in_sizes[1];
    const int nnzB = in_sizes[3];
    const int n    = (int)(sqrt((double)out_size) + 0.5);

    // 1. zero counters via a single graph memset node
    void* cnt_ptr = nullptr;
    cudaGetSymbolAddress(&cnt_ptr, g_cnt);
    cudaMemsetAsync(cnt_ptr, 0, 2 * NMAX * sizeof(int));

    // 2. build buckets
    {
        int items   = (nnzA >> 2) + (nnzB >> 2) + (nnzA & 3) + (nnzB & 3);
        int threads = 256;
        int blocks  = (items + threads - 1) / threads;
        build_kernel<<<blocks, threads>>>(a_idx, a_val, nnzA,
                                          b_idx, b_val, nnzB);
    }
    // 3. compute rows (one block per row; smem allows 8 blocks/SM -> full occ)
    {
        size_t smem = (size_t)n * sizeof(float);
        spmm_row_kernel<<<n, 256, smem>>>(C, n);
    }
}